// round 15
// baseline (speedup 1.0000x reference)
#include <cuda_runtime.h>
#include <cuda_fp16.h>
#include <cstdint>

#define BB   32
#define CC   16
#define HH   256
#define WWID 256
#define PP   144
#define HID  128
#define LL   16384
#define NT   16384     // tiles: 32 positions each
#define NCTA 304

// Scratch for out_p, layout (B, 9, L, 16) fp16 = 151 MB
// element (b, kk, l, c): offset ((b*9 + kk)*LL + l)*16 + c
__device__ __half g_outp[(size_t)BB * PP * LL];

// ---------------- smem byte offsets (per CTA, 2 CTAs/SM) ----------------
#define OFF_B1H 0                  // 128 x 152 x 2B = 38912 (fp16 W1^T)
#define OFF_B2H 38912              // 144 x 136 x 2B = 39168 (fp16 W2^T, n'-order)
#define OFF_A1  78080              // 32 x 152 x 2B = 9728  (A1, fp16)
#define OFF_A2  87808              // 32 x 136 x 2B = 8704  (A2, fp16)
#define OFF_b1  96512              // 512
#define OFF_b2  97024              // 576 (n'-order)
#define SMEM_TOT 97600
#define AS1 152                    // 304B rows: 19*16B -> conflict-free ldmatrix
#define AS2 136                    // 272B rows: 17*16B

typedef unsigned long long u64;

// ---------------- helpers ----------------
__device__ __forceinline__ uint32_t smem_u32(const void* p) {
    uint32_t a;
    asm("{ .reg .u64 t; cvta.to.shared.u64 t, %1; cvt.u32.u64 %0, t; }" : "=r"(a) : "l"(p));
    return a;
}
__device__ __forceinline__ void ldsm4(uint32_t* r, uint32_t a) {
    asm volatile("ldmatrix.sync.aligned.m8n8.x4.shared.b16 {%0,%1,%2,%3}, [%4];"
                 : "=r"(r[0]), "=r"(r[1]), "=r"(r[2]), "=r"(r[3]) : "r"(a));
}
__device__ __forceinline__ void ldsm2(uint32_t* r, uint32_t a) {
    asm volatile("ldmatrix.sync.aligned.m8n8.x2.shared.b16 {%0,%1}, [%2];"
                 : "=r"(r[0]), "=r"(r[1]) : "r"(a));
}
__device__ __forceinline__ void mma_f16(float* d, const uint32_t* a, uint32_t b0, uint32_t b1) {
    asm volatile("mma.sync.aligned.m16n8k16.row.col.f32.f16.f16.f32 "
                 "{%0,%1,%2,%3}, {%4,%5,%6,%7}, {%8,%9}, {%0,%1,%2,%3};"
                 : "+f"(d[0]), "+f"(d[1]), "+f"(d[2]), "+f"(d[3])
                 : "r"(a[0]), "r"(a[1]), "r"(a[2]), "r"(a[3]), "r"(b0), "r"(b1));
}
__device__ __forceinline__ uint32_t pack_rn(float v0, float v1) {
    __half2 h = __float22half2_rn(make_float2(v0, v1));
    return *(uint32_t*)&h;
}
__device__ __forceinline__ int refl(int v, int n) {
    return (v < 0) ? -v : ((v >= n) ? 2 * n - 2 - v : v);
}
// packed fp32x2 (FFMA2) helpers
__device__ __forceinline__ u64 bcast2(float a) {
    u64 r; asm("mov.b64 %0, {%1, %1};" : "=l"(r) : "f"(a)); return r;
}
__device__ __forceinline__ u64 pack2(float a, float b) {
    u64 r; asm("mov.b64 %0, {%1, %2};" : "=l"(r) : "f"(a), "f"(b)); return r;
}
__device__ __forceinline__ void fma2(u64& d, u64 a, u64 b) {
    asm("fma.rn.f32x2 %0, %1, %2, %0;" : "+l"(d) : "l"(a), "l"(b));
}
__device__ __forceinline__ float2 unpack2(u64 a) {
    float2 f; asm("mov.b64 {%0, %1}, %2;" : "=f"(f.x), "=f"(f.y) : "l"(a)); return f;
}

// ---------------------------------------------------------------------------
// Persistent MLP kernel. grid = NCTA(304), 256 threads, 2 CTAs/SM.
// Tile = 32 positions. Warp grid 2m x 4n. fp16 single-pass GEMMs.
// ---------------------------------------------------------------------------
__global__ __launch_bounds__(256, 2)
void mlp_persist(const float* __restrict__ x, const float* __restrict__ W1,
                 const float* __restrict__ b1, const float* __restrict__ W2,
                 const float* __restrict__ b2) {
    extern __shared__ char smem[];
    const uint32_t sb = smem_u32(smem);
    const int tid = threadIdx.x;
    const int wid = tid >> 5, lid = tid & 31;

    float* b1s = (float*)(smem + OFF_b1);
    float* b2s = (float*)(smem + OFF_b2);
    if (tid < 128) b1s[tid] = b1[tid];
    if (tid < 144) b2s[tid] = b2[(tid & 15) * 9 + (tid >> 4)];   // b2s[n'] = b2[p(n')]

    // ---- stage fp16 W1^T ONCE ----
    #pragma unroll 4
    for (int i = 0; i < 72; i++) {
        int e = i * 256 + tid;               // e = k*128 + n
        int k = e >> 7, n = e & 127;
        __half h = __float2half_rn(__ldg(&W1[e]));
        *(uint16_t*)(smem + OFF_B1H + (uint32_t)(n * AS1 + k) * 2) = *(uint16_t*)&h;
    }
    // ---- stage fp16 W2^T ONCE, rows in n' = kk*16 + c order ----
    #pragma unroll 4
    for (int i = 0; i < 72; i++) {
        int e = i * 256 + tid;               // e = k*144 + p
        int k = e / 144, p = e - k * 144;
        int c = p / 9, kk = p - c * 9;
        int np = kk * 16 + c;
        __half h = __float2half_rn(__ldg(&W2[e]));
        *(uint16_t*)(smem + OFF_B2H + (uint32_t)(np * AS2 + k) * 2) = *(uint16_t*)&h;
    }

    // warp tiling constants: 2 m-tiles of 16 rows x 4 n-groups
    const int wm = (wid & 1) * 16;
    const int wn = wid >> 1;
    const int g = lid >> 3, r = lid & 7;
    const int khalf = (g >> 1) * 8;
    const int arow = wm + (g & 1) * 8 + r;
    const int g2 = (lid >> 3) & 1;

    // GEMM2 N-split: 18 n8-tiles over 4 n-warps: [5,5,4,4]
    const int nt2   = (wn < 2) ? 5 : 4;
    const int base2 = wn * 4 + ((wn < 2) ? wn : 2);   // 0,5,10,14

    // gather mapping: pos = tid>>3 (32 pos), oct = tid&7 -> 18 p-elems
    const int pos = tid >> 3;
    const int oct = tid & 7;
    const int pb  = oct * 18;

    float xv[18];

    // ---- prefetch first tile ----
    {
        int t = blockIdx.x;
        int b = t >> 9, rem = t & 511, ho = rem >> 2, wo0 = (rem & 3) * 32;
        const float* xb = x + ((size_t)b * CC + oct * 2) * (HH * WWID);
        int rw[3], cl[3];
        #pragma unroll
        for (int kk = 0; kk < 3; kk++) {
            rw[kk] = refl(2 * ho + kk - 1, HH) * WWID;
            cl[kk] = refl(2 * (wo0 + pos) + kk - 1, WWID);
        }
        #pragma unroll
        for (int ci = 0; ci < 2; ci++) {
            const float* xc = xb + ci * (HH * WWID);
            #pragma unroll
            for (int kh = 0; kh < 3; kh++)
                #pragma unroll
                for (int kw = 0; kw < 3; kw++)
                    xv[ci * 9 + kh * 3 + kw] = __ldg(&xc[rw[kh] + cl[kw]]);
        }
    }

    for (int t = blockIdx.x; t < NT; t += NCTA) {
        const int b = t >> 9, rem = t & 511, ho = rem >> 2, wo0 = (rem & 3) * 32;

        // ---- store A1 (fp16) ----
        #pragma unroll
        for (int i = 0; i < 9; i++) {
            uint32_t hi = pack_rn(xv[2 * i], xv[2 * i + 1]);
            uint32_t off = (uint32_t)(pos * AS1 + pb + 2 * i) * 2;
            *(uint32_t*)(smem + OFF_A1 + off) = hi;
        }
        __syncthreads();   // A1 complete; orders prev GEMM2 before epi1

        // ---- GEMM1: D1[32 x 128], warp covers 16m x 32n ----
        float d1[4][4];
        #pragma unroll
        for (int nj = 0; nj < 4; nj++)
            #pragma unroll
            for (int p = 0; p < 4; p++) d1[nj][p] = 0.f;
        {
            uint32_t pA = sb + OFF_A1 + (uint32_t)(arow * AS1 + khalf) * 2;
            uint32_t pB[2];
            #pragma unroll
            for (int np = 0; np < 2; np++)
                pB[np] = sb + OFF_B1H + (uint32_t)((wn * 32 + np * 16 + (g & 1) * 8 + r) * AS1 + khalf) * 2;

            uint32_t a[4], bA[2][4];
            #pragma unroll
            for (int ks = 0; ks < 9; ks++) {
                const uint32_t ko = ks * 32;
                ldsm4(a, pA + ko);
                #pragma unroll
                for (int np = 0; np < 2; np++) ldsm4(bA[np], pB[np] + ko);
                #pragma unroll
                for (int np = 0; np < 2; np++) {
                    mma_f16(d1[np * 2],     a, bA[np][0], bA[np][2]);
                    mma_f16(d1[np * 2 + 1], a, bA[np][1], bA[np][3]);
                }
            }
        }

        // ---- epi1: relu(D1+b1) fp16 -> A2 (separate buffer, no sync) ----
        {
            const int r0 = lid >> 2;
            const int c0 = (lid & 3) * 2;
            #pragma unroll
            for (int nj = 0; nj < 4; nj++) {
                const int col = wn * 32 + nj * 8 + c0;
                const float bb0 = b1s[col], bb1 = b1s[col + 1];
                float v0 = fmaxf(d1[nj][0] + bb0, 0.f);
                float v1 = fmaxf(d1[nj][1] + bb1, 0.f);
                float v2 = fmaxf(d1[nj][2] + bb0, 0.f);
                float v3 = fmaxf(d1[nj][3] + bb1, 0.f);
                *(uint32_t*)(smem + OFF_A2 + (uint32_t)((wm + r0) * AS2 + col) * 2)     = pack_rn(v0, v1);
                *(uint32_t*)(smem + OFF_A2 + (uint32_t)((wm + r0 + 8) * AS2 + col) * 2) = pack_rn(v2, v3);
            }
        }

        // ---- prefetch next tile (in flight during GEMM2) ----
        {
            int tn = t + NCTA;
            if (tn < NT) {
                int bn = tn >> 9, remn = tn & 511, hon = remn >> 2, wo0n = (remn & 3) * 32;
                const float* xb = x + ((size_t)bn * CC + oct * 2) * (HH * WWID);
                int rw[3], cl[3];
                #pragma unroll
                for (int kk = 0; kk < 3; kk++) {
                    rw[kk] = refl(2 * hon + kk - 1, HH) * WWID;
                    cl[kk] = refl(2 * (wo0n + pos) + kk - 1, WWID);
                }
                #pragma unroll
                for (int ci = 0; ci < 2; ci++) {
                    const float* xc = xb + ci * (HH * WWID);
                    #pragma unroll
                    for (int kh = 0; kh < 3; kh++)
                        #pragma unroll
                        for (int kw = 0; kw < 3; kw++)
                            xv[ci * 9 + kh * 3 + kw] = __ldg(&xc[rw[kh] + cl[kw]]);
                }
            }
        }
        __syncthreads();   // A2 visible to all warps

        // ---- GEMM2: D2[32 x 144 (n'-order)], warp covers 16m x (nt2*8)n ----
        float d2[5][4];
        #pragma unroll
        for (int nj = 0; nj < 5; nj++)
            #pragma unroll
            for (int p = 0; p < 4; p++) d2[nj][p] = 0.f;
        {
            uint32_t pA = sb + OFF_A2 + (uint32_t)(arow * AS2 + khalf) * 2;
            uint32_t pB[2], pS;
            #pragma unroll
            for (int np = 0; np < 2; np++)
                pB[np] = sb + OFF_B2H + (uint32_t)((base2 * 8 + np * 16 + (g & 1) * 8 + r) * AS2 + khalf) * 2;
            pS = sb + OFF_B2H + (uint32_t)(((base2 + 4) * 8 + r) * AS2 + g2 * 8) * 2;

            uint32_t a[4], bA[2][4], sA[2];
            #pragma unroll
            for (int ks = 0; ks < 8; ks++) {
                const uint32_t ko = ks * 32;
                ldsm4(a, pA + ko);
                #pragma unroll
                for (int np = 0; np < 2; np++) ldsm4(bA[np], pB[np] + ko);
                if (nt2 == 5) ldsm2(sA, pS + ko);
                #pragma unroll
                for (int np = 0; np < 2; np++) {
                    mma_f16(d2[np * 2],     a, bA[np][0], bA[np][2]);
                    mma_f16(d2[np * 2 + 1], a, bA[np][1], bA[np][3]);
                }
                if (nt2 == 5) mma_f16(d2[4], a, sA[0], sA[1]);
            }
        }

        // ---- epi2: D2 + b2 -> g_outp (B,9,L,16), coalesced half2 stores ----
        {
            const int r0 = lid >> 2;
            const int c0 = (lid & 3) * 2;
            const int posA = wm + r0;
            const int posB = posA + 8;
            const size_t lbase = (size_t)(ho * 128 + wo0);
            #pragma unroll
            for (int nj = 0; nj < 5; nj++) {
                if (nj < nt2) {
                    const int np = (base2 + nj) * 8 + c0;   // n'
                    const int kk = np >> 4, c = np & 15;
                    const float bb0 = b2s[np], bb1 = b2s[np + 1];
                    __half* cp = g_outp + ((size_t)(b * 9 + kk) * LL + lbase) * 16 + c;
                    *(uint32_t*)(cp + posA * 16) = pack_rn(d2[nj][0] + bb0, d2[nj][1] + bb1);
                    *(uint32_t*)(cp + posB * 16) = pack_rn(d2[nj][2] + bb0, d2[nj][3] + bb1);
                }
            }
        }
    }
}

// ---------------------------------------------------------------------------
// Kernel B: gather-fold + normalize + FFMA2-packed channel mix + softmax +
// modulate.
// ---------------------------------------------------------------------------
__global__ __launch_bounds__(256)
void fold_softmax_kernel(const float* __restrict__ Wc, const float* __restrict__ bc,
                         float* __restrict__ out) {
    __shared__ u64 sWc2[128];   // [op][c]: pair (o=2op, o=2op+1) at channel c
    __shared__ u64 sbc2[8];
    int tid = threadIdx.x;
    if (tid < 128) {
        int op = tid >> 4, c = tid & 15;
        sWc2[tid] = pack2(Wc[(2 * op) * 16 + c], Wc[(2 * op + 1) * 16 + c]);
    }
    if (tid < 8) sbc2[tid] = pack2(bc[2 * tid], bc[2 * tid + 1]);
    __syncthreads();

    const int b = blockIdx.x >> 8;
    const int i = (blockIdx.x & 255) + 1;   // padded row in [1,256]
    const int j = tid + 1;                  // padded col in [1,256]

    // h-axis contributors (block-uniform)
    int kh0, kh1, ho0, ho1; bool h1valid; float cnt_h;
    if (i & 1) { kh0 = 1; ho0 = (i - 1) >> 1; kh1 = 1; ho1 = ho0; h1valid = false; cnt_h = 1.f; }
    else {
        kh0 = 2; ho0 = (i - 2) >> 1;
        kh1 = 0; ho1 = i >> 1;
        h1valid = (ho1 <= 127);
        cnt_h = h1valid ? 2.f : 1.f;
        if (!h1valid) ho1 = 127;
    }
    // w-axis contributors (lane-varying)
    int kw0, kw1, wo0, wo1; bool w1valid; float cnt_w;
    if (j & 1) { kw0 = 1; wo0 = (j - 1) >> 1; kw1 = 1; wo1 = wo0; w1valid = false; cnt_w = 1.f; }
    else {
        kw0 = 2; wo0 = (j - 2) >> 1;
        kw1 = 0; wo1 = j >> 1;
        w1valid = (wo1 <= 127);
        cnt_w = w1valid ? 2.f : 1.f;
        if (!w1valid) wo1 = 127;
    }

    float nrm[16];
    #pragma unroll
    for (int c = 0; c < 16; c++) nrm[c] = 0.f;

    const __half* gb = g_outp + (size_t)b * 9 * LL * 16;
    #define ACC_REC(KK, LV) do {                                               \
        const uint4* rp = (const uint4*)(gb + ((size_t)(KK) * LL + (LV)) * 16);\
        uint4 u0 = __ldg(rp), u1 = __ldg(rp + 1);                              \
        const __half2* h0 = (const __half2*)&u0;                               \
        const __half2* h1 = (const __half2*)&u1;                               \
        _Pragma("unroll")                                                      \
        for (int qq = 0; qq < 4; qq++) {                                       \
            float2 f0 = __half22float2(h0[qq]);                                \
            float2 f1 = __half22float2(h1[qq]);                                \
            nrm[2 * qq]         += f0.x;                                       \
            nrm[2 * qq + 1]     += f0.y;                                       \
            nrm[8 + 2 * qq]     += f1.x;                                       \
            nrm[8 + 2 * qq + 1] += f1.y;                                       \
        }                                                                      \
    } while (0)

    ACC_REC(kh0 * 3 + kw0, ho0 * 128 + wo0);
    if (w1valid) ACC_REC(kh0 * 3 + kw1, ho0 * 128 + wo1);
    if (h1valid) {
        ACC_REC(kh1 * 3 + kw0, ho1 * 128 + wo0);
        if (w1valid) ACC_REC(kh1 * 3 + kw1, ho1 * 128 + wo1);
    }
    #undef ACC_REC

    const float inv = 1.f / (cnt_h * cnt_w + 1e-6f);
    #pragma unroll
    for (int c = 0; c < 16; c++) nrm[c] *= inv;

    // ---- channel mix via packed FFMA2: 8 logit-pairs x 16 channels ----
    u64 lg[8];
    #pragma unroll
    for (int op = 0; op < 8; op++) lg[op] = sbc2[op];
    #pragma unroll
    for (int c = 0; c < 16; c++) {
        const u64 ab = bcast2(nrm[c]);
        #pragma unroll
        for (int op = 0; op < 8; op++) fma2(lg[op], ab, sWc2[op * 16 + c]);
    }
    float logit[16];
    #pragma unroll
    for (int op = 0; op < 8; op++) {
        float2 v = unpack2(lg[op]);
        logit[2 * op] = v.x; logit[2 * op + 1] = v.y;
    }

    float m = logit[0];
    #pragma unroll
    for (int o = 1; o < 16; o++) m = fmaxf(m, logit[o]);
    float e[16], sum = 0.f;
    #pragma unroll
    for (int o = 0; o < 16; o++) { e[o] = __expf(logit[o] - m); sum += e[o]; }
    const float rs = 1.f / sum;

    float* ob = out + (size_t)b * CC * HH * WWID + (size_t)(i - 1) * WWID + (j - 1);
    #pragma unroll
    for (int c = 0; c < 16; c++) ob[(size_t)c * HH * WWID] = nrm[c] * e[c] * rs;
}

// ---------------------------------------------------------------------------
extern "C" void kernel_launch(void* const* d_in, const int* in_sizes, int n_in,
                              void* d_out, int out_size) {
    const float* x  = (const float*)d_in[0];
    const float* W1 = (const float*)d_in[1];
    const float* b1 = (const float*)d_in[2];
    const float* W2 = (const float*)d_in[3];
    const float* b2 = (const float*)d_in[4];
    const float* Wc = (const float*)d_in[5];
    const float* bc = (const float*)d_in[6];
    float* out = (float*)d_out;

    cudaFuncSetAttribute(mlp_persist, cudaFuncAttributeMaxDynamicSharedMemorySize, SMEM_TOT);

    mlp_persist<<<NCTA, 256, SMEM_TOT>>>(x, W1, b1, W2, b2);
    fold_softmax_kernel<<<BB * 256, 256>>>(Wc, bc, out);
}

// round 16
// speedup vs baseline: 1.2859x; 1.2859x over previous
#include <cuda_runtime.h>
#include <cuda_fp16.h>
#include <cstdint>

#define BB   32
#define CC   16
#define HH   256
#define WWID 256
#define PP   144
#define HID  128
#define LL   16384
#define NT   4096      // tiles: 128 positions each (one ho row)
#define NCTA 152

// Scratch for out_p, layout (B, 9, L, 16) fp16 = 151 MB
// element (b, kk, l, c): offset ((b*9 + kk)*LL + l)*16 + c
__device__ __half g_outp[(size_t)BB * PP * LL];

// ---------------- smem byte offsets ----------------
#define OFF_B1H 0                  // 128 x 152 x 2B = 38912 (fp16 W1^T)
#define OFF_B2H 38912              // 144 x 136 x 2B = 39168 (fp16 W2^T, n'-order)
#define OFF_A1  78080              // 128 x 152 x 2B = 38912 (A1, fp16)
#define OFF_A2  116992             // 128 x 136 x 2B = 34816 (A2, fp16)
#define OFF_b1  151808             // 512
#define OFF_b2  152320             // 576 (n'-order)
#define SMEM_TOT 152896
#define AS1 152                    // 304B rows: 19*16B -> conflict-free ldmatrix
#define AS2 136                    // 272B rows: 17*16B

// ---------------- helpers ----------------
__device__ __forceinline__ uint32_t smem_u32(const void* p) {
    uint32_t a;
    asm("{ .reg .u64 t; cvta.to.shared.u64 t, %1; cvt.u32.u64 %0, t; }" : "=r"(a) : "l"(p));
    return a;
}
__device__ __forceinline__ void ldsm4(uint32_t* r, uint32_t a) {
    asm volatile("ldmatrix.sync.aligned.m8n8.x4.shared.b16 {%0,%1,%2,%3}, [%4];"
                 : "=r"(r[0]), "=r"(r[1]), "=r"(r[2]), "=r"(r[3]) : "r"(a));
}
__device__ __forceinline__ void mma_f16(float* d, const uint32_t* a, uint32_t b0, uint32_t b1) {
    asm volatile("mma.sync.aligned.m16n8k16.row.col.f32.f16.f16.f32 "
                 "{%0,%1,%2,%3}, {%4,%5,%6,%7}, {%8,%9}, {%0,%1,%2,%3};"
                 : "+f"(d[0]), "+f"(d[1]), "+f"(d[2]), "+f"(d[3])
                 : "r"(a[0]), "r"(a[1]), "r"(a[2]), "r"(a[3]), "r"(b0), "r"(b1));
}
__device__ __forceinline__ uint32_t pack_rn(float v0, float v1) {
    __half2 h = __float22half2_rn(make_float2(v0, v1));
    return *(uint32_t*)&h;
}
__device__ __forceinline__ int refl(int v, int n) {
    return (v < 0) ? -v : ((v >= n) ? 2 * n - 2 - v : v);
}

// ---------------------------------------------------------------------------
// Persistent MLP kernel. grid = NCTA, 256 threads (8 warps).
// Tile = 128 positions (one full ho row). Each warp owns a 16-row m-stripe
// end-to-end (gather, GEMM1 all-N, epi1, GEMM2 all-N, epi2): the tile loop
// has NO __syncthreads — only intra-warp __syncwarp for smem visibility.
// ---------------------------------------------------------------------------
__global__ __launch_bounds__(256, 1)
void mlp_persist(const float* __restrict__ x, const float* __restrict__ W1,
                 const float* __restrict__ b1, const float* __restrict__ W2,
                 const float* __restrict__ b2) {
    extern __shared__ char smem[];
    const uint32_t sb = smem_u32(smem);
    const int tid = threadIdx.x;
    const int wid = tid >> 5, lid = tid & 31;

    float* b1s = (float*)(smem + OFF_b1);
    float* b2s = (float*)(smem + OFF_b2);
    if (tid < 128) b1s[tid] = b1[tid];
    if (tid < 144) b2s[tid] = b2[(tid & 15) * 9 + (tid >> 4)];   // b2s[n'] = b2[p(n')]

    // ---- stage fp16 W1^T ONCE ----
    #pragma unroll 4
    for (int i = 0; i < 72; i++) {
        int e = i * 256 + tid;               // e = k*128 + n
        int k = e >> 7, n = e & 127;
        __half h = __float2half_rn(__ldg(&W1[e]));
        *(uint16_t*)(smem + OFF_B1H + (uint32_t)(n * AS1 + k) * 2) = *(uint16_t*)&h;
    }
    // ---- stage fp16 W2^T ONCE, rows in n' = kk*16 + c order ----
    #pragma unroll 4
    for (int i = 0; i < 72; i++) {
        int e = i * 256 + tid;               // e = k*144 + p
        int k = e / 144, p = e - k * 144;
        int c = p / 9, kk = p - c * 9;
        int np = kk * 16 + c;
        __half h = __float2half_rn(__ldg(&W2[e]));
        *(uint16_t*)(smem + OFF_B2H + (uint32_t)(np * AS2 + k) * 2) = *(uint16_t*)&h;
    }
    __syncthreads();   // the ONLY CTA-wide barrier

    // warp stripe: rows [wm, wm+16)
    const int wm = wid * 16;
    const int g = lid >> 3, r = lid & 7;
    const int khalf = (g >> 1) * 8;
    const int arow = wm + (g & 1) * 8 + r;
    const int r0 = lid >> 2;
    const int c0 = (lid & 3) * 2;

    // gather mapping: pos = wm + (lid>>1); half = lid&1 -> 72 p-elems
    const int pos  = wm + (lid >> 1);
    const int half = lid & 1;
    const int pb   = half * 72;

    for (int t = blockIdx.x; t < NT; t += NCTA) {
        const int b = t >> 7, ho = t & 127;

        // ---- gather + store A1 rows [wm, wm+16) (warp-local) ----
        {
            const float* xb = x + ((size_t)b * CC + half * 8) * (HH * WWID);
            int rw[3], cl[3];
            #pragma unroll
            for (int kk = 0; kk < 3; kk++) {
                rw[kk] = refl(2 * ho + kk - 1, HH) * WWID;
                cl[kk] = refl(2 * pos + kk - 1, WWID);
            }
            #pragma unroll
            for (int ci = 0; ci < 8; ci++) {
                const float* xc = xb + ci * (HH * WWID);
                float v[9];
                #pragma unroll
                for (int kh = 0; kh < 3; kh++)
                    #pragma unroll
                    for (int kw = 0; kw < 3; kw++)
                        v[kh * 3 + kw] = __ldg(&xc[rw[kh] + cl[kw]]);
                // store 9 values: 4 pairs + handle odd alignment via scalar
                // p base for this ci: pb + ci*9 (parity alternates) -> use
                // scalar 16-bit stores to keep it simple & conflict-light
                #pragma unroll
                for (int e2 = 0; e2 < 9; e2++) {
                    __half hv = __float2half_rn(v[e2]);
                    *(uint16_t*)(smem + OFF_A1 + (uint32_t)(pos * AS1 + pb + ci * 9 + e2) * 2)
                        = *(uint16_t*)&hv;
                }
            }
        }
        __syncwarp();

        // ---- GEMM1: warp stripe 16m x 128n ----
        float d1[16][4];
        #pragma unroll
        for (int nj = 0; nj < 16; nj++)
            #pragma unroll
            for (int p = 0; p < 4; p++) d1[nj][p] = 0.f;
        {
            uint32_t pA = sb + OFF_A1 + (uint32_t)(arow * AS1 + khalf) * 2;
            uint32_t pB[8];
            #pragma unroll
            for (int np = 0; np < 8; np++)
                pB[np] = sb + OFF_B1H + (uint32_t)((np * 16 + (g & 1) * 8 + r) * AS1 + khalf) * 2;

            uint32_t a[4], bA[8][4];
            #pragma unroll
            for (int ks = 0; ks < 9; ks++) {
                const uint32_t ko = ks * 32;
                ldsm4(a, pA + ko);
                #pragma unroll
                for (int np = 0; np < 8; np++) ldsm4(bA[np], pB[np] + ko);
                #pragma unroll
                for (int np = 0; np < 8; np++) {
                    mma_f16(d1[np * 2],     a, bA[np][0], bA[np][2]);
                    mma_f16(d1[np * 2 + 1], a, bA[np][1], bA[np][3]);
                }
            }
        }

        // ---- epi1: relu(D1+b1) fp16 -> A2 rows [wm, wm+16), all 128 cols ----
        #pragma unroll
        for (int nj = 0; nj < 16; nj++) {
            const int col = nj * 8 + c0;
            const float bb0 = b1s[col], bb1 = b1s[col + 1];
            float v0 = fmaxf(d1[nj][0] + bb0, 0.f);
            float v1 = fmaxf(d1[nj][1] + bb1, 0.f);
            float v2 = fmaxf(d1[nj][2] + bb0, 0.f);
            float v3 = fmaxf(d1[nj][3] + bb1, 0.f);
            *(uint32_t*)(smem + OFF_A2 + (uint32_t)((wm + r0) * AS2 + col) * 2)     = pack_rn(v0, v1);
            *(uint32_t*)(smem + OFF_A2 + (uint32_t)((wm + r0 + 8) * AS2 + col) * 2) = pack_rn(v2, v3);
        }
        __syncwarp();

        // ---- GEMM2: warp stripe 16m x 144n (n'-order), 18 n8-tiles ----
        float d2[18][4];
        #pragma unroll
        for (int nj = 0; nj < 18; nj++)
            #pragma unroll
            for (int p = 0; p < 4; p++) d2[nj][p] = 0.f;
        {
            uint32_t pA = sb + OFF_A2 + (uint32_t)(arow * AS2 + khalf) * 2;
            uint32_t pB[9];
            #pragma unroll
            for (int np = 0; np < 9; np++)
                pB[np] = sb + OFF_B2H + (uint32_t)((np * 16 + (g & 1) * 8 + r) * AS2 + khalf) * 2;

            uint32_t a[4], bA[9][4];
            #pragma unroll
            for (int ks = 0; ks < 8; ks++) {
                const uint32_t ko = ks * 32;
                ldsm4(a, pA + ko);
                #pragma unroll
                for (int np = 0; np < 9; np++) ldsm4(bA[np], pB[np] + ko);
                #pragma unroll
                for (int np = 0; np < 9; np++) {
                    mma_f16(d2[np * 2],     a, bA[np][0], bA[np][2]);
                    mma_f16(d2[np * 2 + 1], a, bA[np][1], bA[np][3]);
                }
            }
        }

        // ---- epi2: D2 + b2 -> g_outp (B,9,L,16), coalesced half2 stores ----
        {
            const int posA = wm + r0;
            const int posB = posA + 8;
            const size_t lbase = (size_t)(ho * 128);
            #pragma unroll
            for (int nj = 0; nj < 18; nj++) {
                const int np = nj * 8 + c0;   // n'
                const int kk = np >> 4, c = np & 15;
                const float bb0 = b2s[np], bb1 = b2s[np + 1];
                __half* cp = g_outp + ((size_t)(b * 9 + kk) * LL + lbase) * 16 + c;
                *(uint32_t*)(cp + posA * 16) = pack_rn(d2[nj][0] + bb0, d2[nj][1] + bb1);
                *(uint32_t*)(cp + posB * 16) = pack_rn(d2[nj][2] + bb0, d2[nj][3] + bb1);
            }
        }
        __syncwarp();   // A1/A2 reuse next iteration is warp-local
    }
}

// ---------------------------------------------------------------------------
// Kernel B: gather-fold with zero-weight records skipped + normalize +
// channel mix + softmax + modulate. (R14 version: 71.5us, 54 regs.)
// ---------------------------------------------------------------------------
__global__ __launch_bounds__(256)
void fold_softmax_kernel(const float* __restrict__ Wc, const float* __restrict__ bc,
                         float* __restrict__ out) {
    __shared__ float sWc[256];
    __shared__ float sbc[16];
    int tid = threadIdx.x;
    sWc[tid] = Wc[tid];
    if (tid < 16) sbc[tid] = bc[tid];
    __syncthreads();

    const int b = blockIdx.x >> 8;
    const int i = (blockIdx.x & 255) + 1;   // padded row in [1,256]
    const int j = tid + 1;                  // padded col in [1,256]

    // h-axis contributors (block-uniform)
    int kh0, kh1, ho0, ho1; bool h1valid; float cnt_h;
    if (i & 1) { kh0 = 1; ho0 = (i - 1) >> 1; kh1 = 1; ho1 = ho0; h1valid = false; cnt_h = 1.f; }
    else {
        kh0 = 2; ho0 = (i - 2) >> 1;
        kh1 = 0; ho1 = i >> 1;
        h1valid = (ho1 <= 127);
        cnt_h = h1valid ? 2.f : 1.f;
        if (!h1valid) ho1 = 127;
    }
    // w-axis contributors (lane-varying)
    int kw0, kw1, wo0, wo1; bool w1valid; float cnt_w;
    if (j & 1) { kw0 = 1; wo0 = (j - 1) >> 1; kw1 = 1; wo1 = wo0; w1valid = false; cnt_w = 1.f; }
    else {
        kw0 = 2; wo0 = (j - 2) >> 1;
        kw1 = 0; wo1 = j >> 1;
        w1valid = (wo1 <= 127);
        cnt_w = w1valid ? 2.f : 1.f;
        if (!w1valid) wo1 = 127;
    }

    float nrm[16];
    #pragma unroll
    for (int c = 0; c < 16; c++) nrm[c] = 0.f;

    const __half* gb = g_outp + (size_t)b * 9 * LL * 16;
    #define ACC_REC(KK, LV) do {                                               \
        const uint4* rp = (const uint4*)(gb + ((size_t)(KK) * LL + (LV)) * 16);\
        uint4 u0 = __ldg(rp), u1 = __ldg(rp + 1);                              \
        const __half2* h0 = (const __half2*)&u0;                               \
        const __half2* h1 = (const __half2*)&u1;                               \
        _Pragma("unroll")                                                      \
        for (int qq = 0; qq < 4; qq++) {                                       \
            float2 f0 = __half22float2(h0[qq]);                                \
            float2 f1 = __half22float2(h1[qq]);                                \
            nrm[2 * qq]         += f0.x;                                       \
            nrm[2 * qq + 1]     += f0.y;                                       \
            nrm[8 + 2 * qq]     += f1.x;                                       \
            nrm[8 + 2 * qq + 1] += f1.y;                                       \
        }                                                                      \
    } while (0)

    ACC_REC(kh0 * 3 + kw0, ho0 * 128 + wo0);
    if (w1valid) ACC_REC(kh0 * 3 + kw1, ho0 * 128 + wo1);
    if (h1valid) {
        ACC_REC(kh1 * 3 + kw0, ho1 * 128 + wo0);
        if (w1valid) ACC_REC(kh1 * 3 + kw1, ho1 * 128 + wo1);
    }
    #undef ACC_REC

    const float inv = 1.f / (cnt_h * cnt_w + 1e-6f);
    #pragma unroll
    for (int c = 0; c < 16; c++) nrm[c] *= inv;

    float logit[16];
    #pragma unroll
    for (int o = 0; o < 16; o++) {
        float s = sbc[o];
        #pragma unroll
        for (int c = 0; c < 16; c++) s += sWc[o * 16 + c] * nrm[c];
        logit[o] = s;
    }
    float m = logit[0];
    #pragma unroll
    for (int o = 1; o < 16; o++) m = fmaxf(m, logit[o]);
    float e[16], sum = 0.f;
    #pragma unroll
    for (int o = 0; o < 16; o++) { e[o] = __expf(logit[o] - m); sum += e[o]; }
    const float rs = 1.f / sum;

    float* ob = out + (size_t)b * CC * HH * WWID + (size_t)(i - 1) * WWID + (j - 1);
    #pragma unroll
    for (int c = 0; c < 16; c++) ob[(size_t)c * HH * WWID] = nrm[c] * e[c] * rs;
}

// ---------------------------------------------------------------------------
extern "C" void kernel_launch(void* const* d_in, const int* in_sizes, int n_in,
                              void* d_out, int out_size) {
    const float* x  = (const float*)d_in[0];
    const float* W1 = (const float*)d_in[1];
    const float* b1 = (const float*)d_in[2];
    const float* W2 = (const float*)d_in[3];
    const float* b2 = (const float*)d_in[4];
    const float* Wc = (const float*)d_in[5];
    const float* bc = (const float*)d_in[6];
    float* out = (float*)d_out;

    cudaFuncSetAttribute(mlp_persist, cudaFuncAttributeMaxDynamicSharedMemorySize, SMEM_TOT);

    mlp_persist<<<NCTA, 256, SMEM_TOT>>>(x, W1, b1, W2, b2);
    fold_softmax_kernel<<<BB * 256, 256>>>(Wc, bc, out);
}

// round 17
// speedup vs baseline: 1.3024x; 1.0128x over previous
#include <cuda_runtime.h>
#include <cuda_fp16.h>
#include <cstdint>

#define BB   32
#define CC   16
#define HH   256
#define WWID 256
#define PP   144
#define HID  128
#define LL   16384
#define NT   4096      // tiles: 128 positions each (one ho row)
#define NCTA 152

// Scratch for out_p, layout (B, 9, L, 16) fp16 = 151 MB
// element (b, kk, l, c): offset ((b*9 + kk)*LL + l)*16 + c
__device__ __half g_outp[(size_t)BB * PP * LL];

// ---------------- smem byte offsets ----------------
#define OFF_B1H 0                  // 128 x 152 x 2B = 38912 (fp16 W1^T)
#define OFF_B2H 38912              // 144 x 136 x 2B = 39168 (fp16 W2^T, n'-order)
#define OFF_A1  78080              // 128 x 152 x 2B = 38912 (A1, fp16)
#define OFF_A2  116992             // 128 x 136 x 2B = 34816 (A2, fp16)
#define OFF_b1  151808             // 512
#define OFF_b2  152320             // 576 (n'-order)
#define SMEM_TOT 152896
#define AS1 152                    // 304B rows: 19*16B -> conflict-free ldmatrix
#define AS2 136                    // 272B rows: 17*16B

// ---------------- helpers ----------------
__device__ __forceinline__ uint32_t smem_u32(const void* p) {
    uint32_t a;
    asm("{ .reg .u64 t; cvta.to.shared.u64 t, %1; cvt.u32.u64 %0, t; }" : "=r"(a) : "l"(p));
    return a;
}
__device__ __forceinline__ void ldsm4(uint32_t* r, uint32_t a) {
    asm volatile("ldmatrix.sync.aligned.m8n8.x4.shared.b16 {%0,%1,%2,%3}, [%4];"
                 : "=r"(r[0]), "=r"(r[1]), "=r"(r[2]), "=r"(r[3]) : "r"(a));
}
__device__ __forceinline__ void mma_f16(float* d, const uint32_t* a, uint32_t b0, uint32_t b1) {
    asm volatile("mma.sync.aligned.m16n8k16.row.col.f32.f16.f16.f32 "
                 "{%0,%1,%2,%3}, {%4,%5,%6,%7}, {%8,%9}, {%0,%1,%2,%3};"
                 : "+f"(d[0]), "+f"(d[1]), "+f"(d[2]), "+f"(d[3])
                 : "r"(a[0]), "r"(a[1]), "r"(a[2]), "r"(a[3]), "r"(b0), "r"(b1));
}
__device__ __forceinline__ uint32_t pack_rn(float v0, float v1) {
    __half2 h = __float22half2_rn(make_float2(v0, v1));
    return *(uint32_t*)&h;
}
__device__ __forceinline__ int refl(int v, int n) {
    return (v < 0) ? -v : ((v >= n) ? 2 * n - 2 - v : v);
}

// ---------------------------------------------------------------------------
// Persistent MLP kernel. grid = NCTA, 256 threads (8 warps).
// Tile = 128 positions (one full ho row). Each warp owns a 16-row m-stripe
// end-to-end; no __syncthreads in the tile loop.
// ---------------------------------------------------------------------------
__global__ __launch_bounds__(256, 1)
void mlp_persist(const float* __restrict__ x, const float* __restrict__ W1,
                 const float* __restrict__ b1, const float* __restrict__ W2,
                 const float* __restrict__ b2) {
    extern __shared__ char smem[];
    const uint32_t sb = smem_u32(smem);
    const int tid = threadIdx.x;
    const int wid = tid >> 5, lid = tid & 31;

    float* b1s = (float*)(smem + OFF_b1);
    float* b2s = (float*)(smem + OFF_b2);
    if (tid < 128) b1s[tid] = b1[tid];
    if (tid < 144) b2s[tid] = b2[(tid & 15) * 9 + (tid >> 4)];   // b2s[n'] = b2[p(n')]

    // ---- stage fp16 W1^T ONCE ----
    #pragma unroll 4
    for (int i = 0; i < 72; i++) {
        int e = i * 256 + tid;               // e = k*128 + n
        int k = e >> 7, n = e & 127;
        __half h = __float2half_rn(__ldg(&W1[e]));
        *(uint16_t*)(smem + OFF_B1H + (uint32_t)(n * AS1 + k) * 2) = *(uint16_t*)&h;
    }
    // ---- stage fp16 W2^T ONCE, rows in n' = kk*16 + c order ----
    #pragma unroll 4
    for (int i = 0; i < 72; i++) {
        int e = i * 256 + tid;               // e = k*144 + p
        int k = e / 144, p = e - k * 144;
        int c = p / 9, kk = p - c * 9;
        int np = kk * 16 + c;
        __half h = __float2half_rn(__ldg(&W2[e]));
        *(uint16_t*)(smem + OFF_B2H + (uint32_t)(np * AS2 + k) * 2) = *(uint16_t*)&h;
    }
    __syncthreads();   // the ONLY CTA-wide barrier

    // warp stripe: rows [wm, wm+16)
    const int wm = wid * 16;
    const int g = lid >> 3, r = lid & 7;
    const int khalf = (g >> 1) * 8;
    const int arow = wm + (g & 1) * 8 + r;
    const int r0 = lid >> 2;
    const int c0 = (lid & 3) * 2;

    // gather mapping: pos = wm + (lid>>1); half = lid&1 -> 72 contiguous p
    const int pos  = wm + (lid >> 1);
    const int half = lid & 1;
    const int pb   = half * 72;

    for (int t = blockIdx.x; t < NT; t += NCTA) {
        const int b = t >> 7, ho = t & 127;

        // ---- gather + store A1 rows (warp-local), paired 32-bit stores ----
        {
            const float* xb = x + ((size_t)b * CC + half * 8) * (HH * WWID);
            int rw[3], cl[3];
            #pragma unroll
            for (int kk = 0; kk < 3; kk++) {
                rw[kk] = refl(2 * ho + kk - 1, HH) * WWID;
                cl[kk] = refl(2 * pos + kk - 1, WWID);
            }
            #pragma unroll
            for (int ip = 0; ip < 36; ip++) {
                const int i0 = 2 * ip, i1 = 2 * ip + 1;   // compile-time
                float v0 = __ldg(&xb[(i0 / 9) * (HH * WWID) + rw[(i0 % 9) / 3] + cl[i0 % 3]]);
                float v1 = __ldg(&xb[(i1 / 9) * (HH * WWID) + rw[(i1 % 9) / 3] + cl[i1 % 3]]);
                *(uint32_t*)(smem + OFF_A1 + (uint32_t)(pos * AS1 + pb + i0) * 2)
                    = pack_rn(v0, v1);
            }
        }
        __syncwarp();

        // ---- GEMM1: warp stripe 16m x 128n ----
        float d1[16][4];
        #pragma unroll
        for (int nj = 0; nj < 16; nj++)
            #pragma unroll
            for (int p = 0; p < 4; p++) d1[nj][p] = 0.f;
        {
            uint32_t pA = sb + OFF_A1 + (uint32_t)(arow * AS1 + khalf) * 2;
            uint32_t pB[8];
            #pragma unroll
            for (int np = 0; np < 8; np++)
                pB[np] = sb + OFF_B1H + (uint32_t)((np * 16 + (g & 1) * 8 + r) * AS1 + khalf) * 2;

            uint32_t a[4], bA[8][4];
            #pragma unroll
            for (int ks = 0; ks < 9; ks++) {
                const uint32_t ko = ks * 32;
                ldsm4(a, pA + ko);
                #pragma unroll
                for (int np = 0; np < 8; np++) ldsm4(bA[np], pB[np] + ko);
                #pragma unroll
                for (int np = 0; np < 8; np++) {
                    mma_f16(d1[np * 2],     a, bA[np][0], bA[np][2]);
                    mma_f16(d1[np * 2 + 1], a, bA[np][1], bA[np][3]);
                }
            }
        }

        // ---- epi1: relu(D1+b1) fp16 -> A2 rows [wm, wm+16), all 128 cols ----
        #pragma unroll
        for (int nj = 0; nj < 16; nj++) {
            const int col = nj * 8 + c0;
            const float bb0 = b1s[col], bb1 = b1s[col + 1];
            float v0 = fmaxf(d1[nj][0] + bb0, 0.f);
            float v1 = fmaxf(d1[nj][1] + bb1, 0.f);
            float v2 = fmaxf(d1[nj][2] + bb0, 0.f);
            float v3 = fmaxf(d1[nj][3] + bb1, 0.f);
            *(uint32_t*)(smem + OFF_A2 + (uint32_t)((wm + r0) * AS2 + col) * 2)     = pack_rn(v0, v1);
            *(uint32_t*)(smem + OFF_A2 + (uint32_t)((wm + r0 + 8) * AS2 + col) * 2) = pack_rn(v2, v3);
        }
        __syncwarp();

        // ---- GEMM2: warp stripe 16m x 144n (n'-order), 18 n8-tiles ----
        float d2[18][4];
        #pragma unroll
        for (int nj = 0; nj < 18; nj++)
            #pragma unroll
            for (int p = 0; p < 4; p++) d2[nj][p] = 0.f;
        {
            uint32_t pA = sb + OFF_A2 + (uint32_t)(arow * AS2 + khalf) * 2;
            uint32_t pB[9];
            #pragma unroll
            for (int np = 0; np < 9; np++)
                pB[np] = sb + OFF_B2H + (uint32_t)((np * 16 + (g & 1) * 8 + r) * AS2 + khalf) * 2;

            uint32_t a[4], bA[9][4];
            #pragma unroll
            for (int ks = 0; ks < 8; ks++) {
                const uint32_t ko = ks * 32;
                ldsm4(a, pA + ko);
                #pragma unroll
                for (int np = 0; np < 9; np++) ldsm4(bA[np], pB[np] + ko);
                #pragma unroll
                for (int np = 0; np < 9; np++) {
                    mma_f16(d2[np * 2],     a, bA[np][0], bA[np][2]);
                    mma_f16(d2[np * 2 + 1], a, bA[np][1], bA[np][3]);
                }
            }
        }

        // ---- epi2: D2 + b2 -> g_outp (B,9,L,16), coalesced half2 stores ----
        {
            const int posA = wm + r0;
            const int posB = posA + 8;
            const size_t lbase = (size_t)(ho * 128);
            #pragma unroll
            for (int nj = 0; nj < 18; nj++) {
                const int np = nj * 8 + c0;   // n'
                const int kk = np >> 4, c = np & 15;
                const float bb0 = b2s[np], bb1 = b2s[np + 1];
                __half* cp = g_outp + ((size_t)(b * 9 + kk) * LL + lbase) * 16 + c;
                *(uint32_t*)(cp + posA * 16) = pack_rn(d2[nj][0] + bb0, d2[nj][1] + bb1);
                *(uint32_t*)(cp + posB * 16) = pack_rn(d2[nj][2] + bb0, d2[nj][3] + bb1);
            }
        }
        __syncwarp();   // A1/A2 reuse next iteration is warp-local
    }
}

// ---------------------------------------------------------------------------
// Kernel B: gather-fold + normalize + channel mix (float4 weight loads) +
// softmax + modulate.
// ---------------------------------------------------------------------------
__global__ __launch_bounds__(256)
void fold_softmax_kernel(const float* __restrict__ Wc, const float* __restrict__ bc,
                         float* __restrict__ out) {
    __shared__ float sWc[256];
    __shared__ float sbc[16];
    int tid = threadIdx.x;
    sWc[tid] = Wc[tid];
    if (tid < 16) sbc[tid] = bc[tid];
    __syncthreads();

    const int b = blockIdx.x >> 8;
    const int i = (blockIdx.x & 255) + 1;   // padded row in [1,256]
    const int j = tid + 1;                  // padded col in [1,256]

    // h-axis contributors (block-uniform)
    int kh0, kh1, ho0, ho1; bool h1valid; float cnt_h;
    if (i & 1) { kh0 = 1; ho0 = (i - 1) >> 1; kh1 = 1; ho1 = ho0; h1valid = false; cnt_h = 1.f; }
    else {
        kh0 = 2; ho0 = (i - 2) >> 1;
        kh1 = 0; ho1 = i >> 1;
        h1valid = (ho1 <= 127);
        cnt_h = h1valid ? 2.f : 1.f;
        if (!h1valid) ho1 = 127;
    }
    // w-axis contributors (lane-varying)
    int kw0, kw1, wo0, wo1; bool w1valid; float cnt_w;
    if (j & 1) { kw0 = 1; wo0 = (j - 1) >> 1; kw1 = 1; wo1 = wo0; w1valid = false; cnt_w = 1.f; }
    else {
        kw0 = 2; wo0 = (j - 2) >> 1;
        kw1 = 0; wo1 = j >> 1;
        w1valid = (wo1 <= 127);
        cnt_w = w1valid ? 2.f : 1.f;
        if (!w1valid) wo1 = 127;
    }

    float nrm[16];
    #pragma unroll
    for (int c = 0; c < 16; c++) nrm[c] = 0.f;

    const __half* gb = g_outp + (size_t)b * 9 * LL * 16;
    #define ACC_REC(KK, LV) do {                                               \
        const uint4* rp = (const uint4*)(gb + ((size_t)(KK) * LL + (LV)) * 16);\
        uint4 u0 = __ldg(rp), u1 = __ldg(rp + 1);                              \
        const __half2* h0 = (const __half2*)&u0;                               \
        const __half2* h1 = (const __half2*)&u1;                               \
        _Pragma("unroll")                                                      \
        for (int qq = 0; qq < 4; qq++) {                                       \
            float2 f0 = __half22float2(h0[qq]);                                \
            float2 f1 = __half22float2(h1[qq]);                                \
            nrm[2 * qq]         += f0.x;                                       \
            nrm[2 * qq + 1]     += f0.y;                                       \
            nrm[8 + 2 * qq]     += f1.x;                                       \
            nrm[8 + 2 * qq + 1] += f1.y;                                       \
        }                                                                      \
    } while (0)

    ACC_REC(kh0 * 3 + kw0, ho0 * 128 + wo0);
    if (w1valid) ACC_REC(kh0 * 3 + kw1, ho0 * 128 + wo1);
    if (h1valid) {
        ACC_REC(kh1 * 3 + kw0, ho1 * 128 + wo0);
        if (w1valid) ACC_REC(kh1 * 3 + kw1, ho1 * 128 + wo1);
    }
    #undef ACC_REC

    const float inv = 1.f / (cnt_h * cnt_w + 1e-6f);
    #pragma unroll
    for (int c = 0; c < 16; c++) nrm[c] *= inv;

    // ---- channel mix: float4 weight loads (LDS.128), fp32 FMA ----
    float logit[16];
    #pragma unroll
    for (int o = 0; o < 16; o++) {
        const float4* wr = (const float4*)&sWc[o * 16];
        float s = sbc[o];
        #pragma unroll
        for (int q4 = 0; q4 < 4; q4++) {
            float4 w = wr[q4];
            s += w.x * nrm[4 * q4]     + w.y * nrm[4 * q4 + 1]
               + w.z * nrm[4 * q4 + 2] + w.w * nrm[4 * q4 + 3];
        }
        logit[o] = s;
    }

    float m = logit[0];
    #pragma unroll
    for (int o = 1; o < 16; o++) m = fmaxf(m, logit[o]);
    float e[16], sum = 0.f;
    #pragma unroll
    for (int o = 0; o < 16; o++) { e[o] = __expf(logit[o] - m); sum += e[o]; }
    const float rs = 1.f / sum;

    float* ob = out + (size_t)b * CC * HH * WWID + (size_t)(i - 1) * WWID + (j - 1);
    #pragma unroll
    for (int c = 0; c < 16; c++) ob[(size_t)c * HH * WWID] = nrm[c] * e[c] * rs;
}

// ---------------------------------------------------------------------------
extern "C" void kernel_launch(void* const* d_in, const int* in_sizes, int n_in,
                              void* d_out, int out_size) {
    const float* x  = (const float*)d_in[0];
    const float* W1 = (const float*)d_in[1];
    const float* b1 = (const float*)d_in[2];
    const float* W2 = (const float*)d_in[3];
    const float* b2 = (const float*)d_in[4];
    const float* Wc = (const float*)d_in[5];
    const float* bc = (const float*)d_in[6];
    float* out = (float*)d_out;

    cudaFuncSetAttribute(mlp_persist, cudaFuncAttributeMaxDynamicSharedMemorySize, SMEM_TOT);

    mlp_persist<<<NCTA, 256, SMEM_TOT>>>(x, W1, b1, W2, b2);
    fold_softmax_kernel<<<BB * 256, 256>>>(Wc, bc, out);
}